// round 16
// baseline (speedup 1.0000x reference)
#include <cuda_runtime.h>
#include <cuda_bf16.h>

#define H            128
#define BASKET_LEN   200
#define NT           1024          // 32 warps per block
#define WARPS        32
#define GATHER_BLKS  7             // 7*32 = 224 warps >= 200 items
#define NB           (GATHER_BLKS + 1)   // +1 block for gh matvec

// Scratch (device globals; no allocation). All slots written every launch.
__device__ float        g_part[GATHER_BLKS][H];
__device__ float        g_gh[3 * H];
__device__ unsigned int g_ticket;   // zero at load; reset by last block each launch

__device__ __forceinline__ float fast_sigmoid(float x) {
    return __fdividef(1.0f, 1.0f + __expf(-x));
}
__device__ __forceinline__ float fast_tanh(float x) {
    const float t = __expf(-2.0f * x);
    return __fdividef(1.0f - t, 1.0f + t);
}

// 12-row matvec as 3 groups of 4, software-pipelined with a 2-deep buffer:
// group g+1's loads are issued before group g's reduce, hiding 2 of 3 L2 rounds.
// Peak live: 8 float4 weight regs (vs 12 in the failed matvec12).
__device__ __forceinline__ void matvec12_pipe(const float4* __restrict__ Wv,
                                              int r0, int lane, float4 v,
                                              const float* __restrict__ bias,
                                              float* __restrict__ dst)
{
    float4 buf[2][4];

    #pragma unroll
    for (int j = 0; j < 4; j++)
        buf[0][j] = __ldg(&Wv[(size_t)(r0 + j) * 32 + lane]);

    #pragma unroll
    for (int g = 0; g < 3; g++) {
        if (g < 2) {
            #pragma unroll
            for (int j = 0; j < 4; j++)
                buf[(g + 1) & 1][j] =
                    __ldg(&Wv[(size_t)(r0 + (g + 1) * 4 + j) * 32 + lane]);
        }
        float p0 = buf[g & 1][0].x * v.x + buf[g & 1][0].y * v.y + buf[g & 1][0].z * v.z + buf[g & 1][0].w * v.w;
        float p1 = buf[g & 1][1].x * v.x + buf[g & 1][1].y * v.y + buf[g & 1][1].z * v.z + buf[g & 1][1].w * v.w;
        float p2 = buf[g & 1][2].x * v.x + buf[g & 1][2].y * v.y + buf[g & 1][2].z * v.z + buf[g & 1][2].w * v.w;
        float p3 = buf[g & 1][3].x * v.x + buf[g & 1][3].y * v.y + buf[g & 1][3].z * v.z + buf[g & 1][3].w * v.w;

        #pragma unroll
        for (int off = 16; off; off >>= 1) {
            p0 += __shfl_xor_sync(0xFFFFFFFFu, p0, off);
            p1 += __shfl_xor_sync(0xFFFFFFFFu, p1, off);
            p2 += __shfl_xor_sync(0xFFFFFFFFu, p2, off);
            p3 += __shfl_xor_sync(0xFFFFFFFFu, p3, off);
        }
        if (lane == 0) {
            const int rb = r0 + g * 4;
            dst[rb + 0] = p0 + __ldg(&bias[rb + 0]);
            dst[rb + 1] = p1 + __ldg(&bias[rb + 1]);
            dst[rb + 2] = p2 + __ldg(&bias[rb + 2]);
            dst[rb + 3] = p3 + __ldg(&bias[rb + 3]);
        }
    }
}

__global__ __launch_bounds__(NT, 1)
void encoder_rnn_fused(const int* __restrict__ basket,
                       const float* __restrict__ hidden,
                       const float* __restrict__ emb_table,
                       const float* __restrict__ w_ih,
                       const float* __restrict__ w_hh,
                       const float* __restrict__ b_ih,
                       const float* __restrict__ b_hh,
                       float* __restrict__ out,
                       int out_size)
{
    __shared__ float s_red[WARPS * H];      // 16 KB: gather per-warp rows
    __shared__ float s_emb[H];
    __shared__ float s_gi[3 * H];
    __shared__ float s_h[H];
    __shared__ unsigned s_last;

    const int tid  = threadIdx.x;
    const int lane = tid & 31;
    const int w    = tid >> 5;
    const int blk  = blockIdx.x;

    if (blk < GATHER_BLKS) {
        // ---- Phase A: one warp per basket item, full 512B row per LDG.128 ----
        const int item = blk * WARPS + w;
        float4 v = make_float4(0.f, 0.f, 0.f, 0.f);
        if (item < BASKET_LEN) {
            const long idx = (long)__ldg(&basket[item]);
            v = __ldg(&reinterpret_cast<const float4*>(emb_table)[idx * 32 + lane]);
        }
        reinterpret_cast<float4*>(s_red)[w * 32 + lane] = v;
        __syncthreads();
        if (tid < H) {
            float a = 0.f;
            #pragma unroll
            for (int ww = 0; ww < WARPS; ww++) a += s_red[ww * H + tid];
            g_part[blk][tid] = a;
        }
    } else {
        // ---- Phase A': gh = w_hh @ h + b_hh — pipelined 4-row groups ----
        const float4 h4 = __ldg(&reinterpret_cast<const float4*>(hidden)[lane]);
        matvec12_pipe(reinterpret_cast<const float4*>(w_hh), w * 12, lane, h4,
                      b_hh, g_gh);
    }

    // ---- Ticket: last-arriving block runs the tail ----
    __threadfence();
    __syncthreads();
    if (tid == 0) s_last = (atomicAdd(&g_ticket, 1u) == NB - 1);
    __syncthreads();
    if (!s_last) return;
    __threadfence();   // acquire: make peers' g_part / g_gh visible

    // ---- Phase B: reduce partials -> emb; load h; prefetch g_gh ----
    float hr = 0.f, hz = 0.f, hn = 0.f;
    if (tid < H) {
        float a = 0.f;
        #pragma unroll
        for (int b = 0; b < GATHER_BLKS; b++) a += g_part[b][tid];
        s_emb[tid] = a * (1.0f / (float)H);
        s_h[tid]   = hidden[tid];
        hr = g_gh[tid];
        hz = g_gh[H + tid];
        hn = g_gh[2 * H + tid];
    }
    __syncthreads();

    // ---- Phase C: gi = w_ih @ emb + b_ih — pipelined 4-row groups ----
    {
        const float4 e4 = reinterpret_cast<const float4*>(s_emb)[lane];
        matvec12_pipe(reinterpret_cast<const float4*>(w_ih), w * 12, lane, e4,
                      b_ih, s_gi);
    }
    __syncthreads();

    // ---- Phase D: GRU gates + replicated output ----
    if (tid < H) {
        const float i_r = s_gi[tid];
        const float i_z = s_gi[H + tid];
        const float i_n = s_gi[2 * H + tid];

        const float r = fast_sigmoid(i_r + hr);
        const float z = fast_sigmoid(i_z + hz);
        const float n = fast_tanh(i_n + r * hn);
        const float h_new = (1.0f - z) * n + z * s_h[tid];

        for (int o = tid; o < out_size; o += H)
            out[o] = h_new;
    }

    if (tid == 0) g_ticket = 0;   // reset for next graph replay
}

extern "C" void kernel_launch(void* const* d_in, const int* in_sizes, int n_in,
                              void* d_out, int out_size)
{
    const int*   basket    = (const int*)  d_in[0];
    const float* hidden    = (const float*)d_in[1];
    const float* emb_table = (const float*)d_in[2];
    const float* w_ih      = (const float*)d_in[3];
    const float* w_hh      = (const float*)d_in[4];
    const float* b_ih      = (const float*)d_in[5];
    const float* b_hh      = (const float*)d_in[6];
    float* out = (float*)d_out;

    encoder_rnn_fused<<<NB, NT>>>(basket, hidden, emb_table,
                                  w_ih, w_hh, b_ih, b_hh,
                                  out, out_size);
}

// round 17
// speedup vs baseline: 1.5828x; 1.5828x over previous
#include <cuda_runtime.h>
#include <cuda_bf16.h>

#define H            128
#define BASKET_LEN   200
#define NT           1024          // 32 warps per block
#define WARPS        32
#define GATHER_BLKS  7             // 7*32 = 224 warps >= 200 items
#define GH_BLKS      3             // each gh block: 128 rows, ONE 4-row group per warp
#define NB           (GATHER_BLKS + GH_BLKS)

// Scratch (device globals; no allocation). All slots written every launch.
__device__ float        g_part[GATHER_BLKS][H];
__device__ float        g_gh[3 * H];
__device__ unsigned int g_ticket;   // zero at load; reset by last block each launch

__device__ __forceinline__ float fast_sigmoid(float x) {
    return __fdividef(1.0f, 1.0f + __expf(-x));
}
__device__ __forceinline__ float fast_tanh(float x) {
    const float t = __expf(-2.0f * x);
    return __fdividef(1.0f - t, 1.0f + t);
}

__global__ __launch_bounds__(NT, 1)
void encoder_rnn_fused(const int* __restrict__ basket,
                       const float* __restrict__ hidden,
                       const float* __restrict__ emb_table,
                       const float* __restrict__ w_ih,
                       const float* __restrict__ w_hh,
                       const float* __restrict__ b_ih,
                       const float* __restrict__ b_hh,
                       float* __restrict__ out,
                       int out_size)
{
    __shared__ float s_red[WARPS * H];      // 16 KB: gather per-warp rows
    __shared__ float s_emb[H];
    __shared__ float s_gi[3 * H];
    __shared__ float s_h[H];
    __shared__ unsigned s_last;

    const int tid  = threadIdx.x;
    const int lane = tid & 31;
    const int w    = tid >> 5;
    const int blk  = blockIdx.x;

    if (blk < GATHER_BLKS) {
        // ---- Phase A: one warp per basket item, full 512B row per LDG.128 ----
        const int item = blk * WARPS + w;
        float4 v = make_float4(0.f, 0.f, 0.f, 0.f);
        if (item < BASKET_LEN) {
            const long idx = (long)__ldg(&basket[item]);
            v = __ldg(&reinterpret_cast<const float4*>(emb_table)[idx * 32 + lane]);
        }
        reinterpret_cast<float4*>(s_red)[w * 32 + lane] = v;
        __syncthreads();
        if (tid < H) {
            float a = 0.f;
            #pragma unroll
            for (int ww = 0; ww < WARPS; ww++) a += s_red[ww * H + tid];
            g_part[blk][tid] = a;
        }
    } else {
        // ---- Phase A': gh slice — ONE 4-row group per warp (single L2 round) ----
        const int gb = blk - GATHER_BLKS;            // 0..2
        const float4 h4 = __ldg(&reinterpret_cast<const float4*>(hidden)[lane]);
        const int r0 = gb * 128 + w * 4;             // 3 blocks x 32 warps x 4 rows = 384
        float p0, p1, p2, p3;
        {
            const float4 a = __ldg(&reinterpret_cast<const float4*>(w_hh)[(size_t)(r0 + 0) * 32 + lane]);
            const float4 b = __ldg(&reinterpret_cast<const float4*>(w_hh)[(size_t)(r0 + 1) * 32 + lane]);
            const float4 c = __ldg(&reinterpret_cast<const float4*>(w_hh)[(size_t)(r0 + 2) * 32 + lane]);
            const float4 d = __ldg(&reinterpret_cast<const float4*>(w_hh)[(size_t)(r0 + 3) * 32 + lane]);
            p0 = a.x * h4.x + a.y * h4.y + a.z * h4.z + a.w * h4.w;
            p1 = b.x * h4.x + b.y * h4.y + b.z * h4.z + b.w * h4.w;
            p2 = c.x * h4.x + c.y * h4.y + c.z * h4.z + c.w * h4.w;
            p3 = d.x * h4.x + d.y * h4.y + d.z * h4.z + d.w * h4.w;
        }
        #pragma unroll
        for (int off = 16; off; off >>= 1) {
            p0 += __shfl_xor_sync(0xFFFFFFFFu, p0, off);
            p1 += __shfl_xor_sync(0xFFFFFFFFu, p1, off);
            p2 += __shfl_xor_sync(0xFFFFFFFFu, p2, off);
            p3 += __shfl_xor_sync(0xFFFFFFFFu, p3, off);
        }
        if (lane == 0) {
            g_gh[r0 + 0] = p0 + __ldg(&b_hh[r0 + 0]);
            g_gh[r0 + 1] = p1 + __ldg(&b_hh[r0 + 1]);
            g_gh[r0 + 2] = p2 + __ldg(&b_hh[r0 + 2]);
            g_gh[r0 + 3] = p3 + __ldg(&b_hh[r0 + 3]);
        }
    }

    // ---- Ticket: last-arriving block runs the tail ----
    __threadfence();
    __syncthreads();
    if (tid == 0) s_last = (atomicAdd(&g_ticket, 1u) == NB - 1);
    __syncthreads();
    if (!s_last) return;
    __threadfence();   // acquire: make peers' g_part / g_gh visible

    // ---- Phase B: reduce partials -> emb; load h; prefetch g_gh ----
    float hr = 0.f, hz = 0.f, hn = 0.f;
    if (tid < H) {
        float a = 0.f;
        #pragma unroll
        for (int b = 0; b < GATHER_BLKS; b++) a += g_part[b][tid];
        s_emb[tid] = a * (1.0f / (float)H);
        s_h[tid]   = hidden[tid];
        hr = g_gh[tid];
        hz = g_gh[H + tid];
        hn = g_gh[2 * H + tid];
    }
    __syncthreads();

    // ---- Phase C: gi = w_ih @ emb + b_ih (32 warps x 12 rows, 4-row groups) ----
    {
        const float4 e4 = reinterpret_cast<const float4*>(s_emb)[lane];
        const int r0 = w * 12;
        for (int rr = 0; rr < 12; rr += 4) {
            float p0, p1, p2, p3;
            {
                const float4 a = __ldg(&reinterpret_cast<const float4*>(w_ih)[(size_t)(r0 + rr + 0) * 32 + lane]);
                const float4 b = __ldg(&reinterpret_cast<const float4*>(w_ih)[(size_t)(r0 + rr + 1) * 32 + lane]);
                const float4 c = __ldg(&reinterpret_cast<const float4*>(w_ih)[(size_t)(r0 + rr + 2) * 32 + lane]);
                const float4 d = __ldg(&reinterpret_cast<const float4*>(w_ih)[(size_t)(r0 + rr + 3) * 32 + lane]);
                p0 = a.x * e4.x + a.y * e4.y + a.z * e4.z + a.w * e4.w;
                p1 = b.x * e4.x + b.y * e4.y + b.z * e4.z + b.w * e4.w;
                p2 = c.x * e4.x + c.y * e4.y + c.z * e4.z + c.w * e4.w;
                p3 = d.x * e4.x + d.y * e4.y + d.z * e4.z + d.w * e4.w;
            }
            #pragma unroll
            for (int off = 16; off; off >>= 1) {
                p0 += __shfl_xor_sync(0xFFFFFFFFu, p0, off);
                p1 += __shfl_xor_sync(0xFFFFFFFFu, p1, off);
                p2 += __shfl_xor_sync(0xFFFFFFFFu, p2, off);
                p3 += __shfl_xor_sync(0xFFFFFFFFu, p3, off);
            }
            if (lane == 0) {
                s_gi[r0 + rr + 0] = p0 + __ldg(&b_ih[r0 + rr + 0]);
                s_gi[r0 + rr + 1] = p1 + __ldg(&b_ih[r0 + rr + 1]);
                s_gi[r0 + rr + 2] = p2 + __ldg(&b_ih[r0 + rr + 2]);
                s_gi[r0 + rr + 3] = p3 + __ldg(&b_ih[r0 + rr + 3]);
            }
        }
    }
    __syncthreads();

    // ---- Phase D: GRU gates + replicated output ----
    if (tid < H) {
        const float i_r = s_gi[tid];
        const float i_z = s_gi[H + tid];
        const float i_n = s_gi[2 * H + tid];

        const float r = fast_sigmoid(i_r + hr);
        const float z = fast_sigmoid(i_z + hz);
        const float n = fast_tanh(i_n + r * hn);
        const float h_new = (1.0f - z) * n + z * s_h[tid];

        for (int o = tid; o < out_size; o += H)
            out[o] = h_new;
    }

    if (tid == 0) g_ticket = 0;   // reset for next graph replay
}

extern "C" void kernel_launch(void* const* d_in, const int* in_sizes, int n_in,
                              void* d_out, int out_size)
{
    const int*   basket    = (const int*)  d_in[0];
    const float* hidden    = (const float*)d_in[1];
    const float* emb_table = (const float*)d_in[2];
    const float* w_ih      = (const float*)d_in[3];
    const float* w_hh      = (const float*)d_in[4];
    const float* b_ih      = (const float*)d_in[5];
    const float* b_hh      = (const float*)d_in[6];
    float* out = (float*)d_out;

    encoder_rnn_fused<<<NB, NT>>>(basket, hidden, emb_table,
                                  w_ih, w_hh, b_ih, b_hh,
                                  out, out_size);
}